// round 13
// baseline (speedup 1.0000x reference)
#include <cuda_runtime.h>
#include <cuda_fp16.h>
#include <math.h>
#include <stdint.h>

// MoE: B=8, N=1024, E=1024, H=1536, X=8, K=2
#define B_  8
#define N_  1024
#define T_  (B_*N_)      // 8192 tokens
#define E_  1024
#define H_  1536
#define X_  8
#define K_  2
#define TS_ (T_*K_)      // 16384 (token, slot) pairs

// ---- scratch (allocation-free: __device__ globals; zero-init at load,
//      re-zeroed by reduce_kernel each launch) ----
__device__ int    g_count[X_];
__device__ int    g_ticket;
__device__ int    g_done[X_ * 64];                       // G1 nb-completions per (z, rb)
__device__ int    g_slots[X_ * T_];                      // slot id = t*K + k
__device__ __half g_xh[(size_t)T_ * E_];                 // x in fp16
__device__ __half g_W1T[(size_t)X_ * H_ * E_];           // [x][h][e] fp16 (B n-major)
__device__ __half g_W2T[(size_t)X_ * E_ * H_];           // [x][e][h] fp16
__device__ __half g_hh[(size_t)TS_ * H_];                // post-GELU hidden (fp16)
__device__ __half g_yh[(size_t)TS_ * E_];                // expert output (fp16)

// ============================ helpers =======================================
__device__ __forceinline__ uint32_t smem_u32(const void* p) {
    uint32_t a;
    asm("{ .reg .u64 t; cvta.to.shared.u64 t, %1; cvt.u32.u64 %0, t; }" : "=r"(a) : "l"(p));
    return a;
}
__device__ __forceinline__ void cp16z(uint32_t dst, const void* src, uint32_t sz) {
    asm volatile("cp.async.cg.shared.global [%0], [%1], 16, %2;"
                 :: "r"(dst), "l"(src), "r"(sz) : "memory");
}
__device__ __forceinline__ void cp16(uint32_t dst, const void* src) {
    asm volatile("cp.async.cg.shared.global [%0], [%1], 16;"
                 :: "r"(dst), "l"(src) : "memory");
}
#define CP_COMMIT() asm volatile("cp.async.commit_group;" ::: "memory")
#define CP_WAIT0()  asm volatile("cp.async.wait_group 0;" ::: "memory")
#define CP_WAIT1()  asm volatile("cp.async.wait_group 1;" ::: "memory")

__device__ __forceinline__ void mma_f16(float* c, const uint32_t* a, const uint32_t* b) {
    asm volatile("mma.sync.aligned.m16n8k16.row.col.f32.f16.f16.f32 "
                 "{%0,%1,%2,%3}, {%4,%5,%6,%7}, {%8,%9}, {%0,%1,%2,%3};"
                 : "+f"(c[0]), "+f"(c[1]), "+f"(c[2]), "+f"(c[3])
                 : "r"(a[0]), "r"(a[1]), "r"(a[2]), "r"(a[3]), "r"(b[0]), "r"(b[1]));
}

__device__ __forceinline__ float gelu_erf(float v) {
    return 0.5f * v * (1.0f + erff(v * 0.70710678118654752f));
}

// ---------------------------------------------------------------------------
// Fused prep kernel (unchanged from R12): router+cvt | W1 transpose | W2 transpose
#define PREP_RTR    (T_ / 8)                  // 1024
#define PREP_TPB    768
#define PREP_W1     PREP_RTR
#define PREP_W2     (PREP_RTR + PREP_TPB * X_)
#define PREP_TOTAL  (PREP_RTR + 2 * PREP_TPB * X_)

__device__ __forceinline__ void transpose_body(
    const float* __restrict__ in, __half* __restrict__ out,
    int R, int C, int z, int cb, int rb, float (*t)[33], int tid) {
    size_t base = (size_t)z * R * C;
    in  += base; out += base;
    const int c0 = cb * 32, r0 = rb * 64;
    const int tx = tid & 31, ty = tid >> 5;
#pragma unroll
    for (int j = 0; j < 64; j += 8)
        t[ty + j][tx] = in[(size_t)(r0 + ty + j) * C + c0 + tx];
    __syncthreads();
#pragma unroll
    for (int j = 0; j < 32; j += 8) {
        int c = ty + j;
        __half2 hv = __floats2half2_rn(t[2 * tx][c], t[2 * tx + 1][c]);
        *(__half2*)(out + (size_t)(c0 + c) * R + r0 + 2 * tx) = hv;
    }
}

__global__ __launch_bounds__(256)
void prep_kernel(const float* __restrict__ x,
                 const float* __restrict__ Wr,
                 const float* __restrict__ br,
                 float* __restrict__ out_idx,
                 const float* __restrict__ W1,
                 const float* __restrict__ W2) {
    __shared__ float t[64][33];
    const int bx  = blockIdx.x;
    const int tid = threadIdx.x;

    if (bx >= PREP_RTR) {
        int idx, R, C;
        const float* in; __half* out;
        if (bx < PREP_W2) { idx = bx - PREP_W1; in = W1; out = g_W1T; R = E_; C = H_; }
        else              { idx = bx - PREP_W2; in = W2; out = g_W2T; R = H_; C = E_; }
        const int cbn = C / 32;
        const int z   = idx / PREP_TPB;
        const int rem = idx - z * PREP_TPB;
        const int rb  = rem / cbn;
        const int cb  = rem - rb * cbn;
        transpose_body(in, out, R, C, z, cb, rb, t, tid);
        return;
    }

    const int gwarp = bx * 8 + (tid >> 5);
    const int lane  = tid & 31;
    const float* xr = x + (size_t)gwarp * E_;
    __half* xh = g_xh + (size_t)gwarp * E_;

    float acc[X_];
#pragma unroll
    for (int j = 0; j < X_; j++) acc[j] = 0.f;
    for (int e = lane * 2; e < E_; e += 64) {
        float2 xv = *(const float2*)(xr + e);
        *(__half2*)(xh + e) = __floats2half2_rn(xv.x, xv.y);
#pragma unroll
        for (int rep = 0; rep < 2; rep++) {
            float v = rep ? xv.y : xv.x;
            const float4* w4 = (const float4*)(Wr + (size_t)(e + rep) * X_);
            float4 w0 = w4[0], w1 = w4[1];
            acc[0] += v * w0.x; acc[1] += v * w0.y;
            acc[2] += v * w0.z; acc[3] += v * w0.w;
            acc[4] += v * w1.x; acc[5] += v * w1.y;
            acc[6] += v * w1.z; acc[7] += v * w1.w;
        }
    }
#pragma unroll
    for (int j = 0; j < X_; j++)
#pragma unroll
        for (int off = 16; off > 0; off >>= 1)
            acc[j] += __shfl_down_sync(0xffffffffu, acc[j], off);

    if (lane == 0) {
        float v0 = -3.0e38f, v1 = -3.0e38f;
        int   i0 = 0,        i1 = 0;
#pragma unroll
        for (int j = 0; j < X_; j++) {
            float v = acc[j] + br[j];
            if (v > v0)      { v1 = v0; i1 = i0; v0 = v; i0 = j; }
            else if (v > v1) { v1 = v;  i1 = j; }
        }
        if (out_idx) {
            out_idx[gwarp * K_ + 0] = (float)i0;
            out_idx[gwarp * K_ + 1] = (float)i1;
        }
        int p0 = atomicAdd(&g_count[i0], 1);
        g_slots[i0 * T_ + p0] = gwarp * K_ + 0;
        int p1 = atomicAdd(&g_count[i1], 1);
        g_slots[i1 * T_ + p1] = gwarp * K_ + 1;
    }
}

// ---------------------------------------------------------------------------
// GEMM tile body (champion mainloop, blockIdx replaced by ticket coords).
// FIRST: gelu(xh @ W1T^T + b1) -> g_hh, then signal g_done[z][by].
// else : g_hh @ W2T^T + b2 -> g_yh (caller spin-waits before invoking).
#define BKH      64
#define OP_WORDS (128 * 36)
#define STAGE_B  (2 * OP_WORDS * 4)
#define NSTAGE   3
#define GEMM_SMEM (1024 + NSTAGE * STAGE_B)

template<int KDIM, int NDIM, bool FIRST>
__device__ __forceinline__ void gemm_tile(const int z, const int by, const int bx,
                                          const __half* __restrict__ WT_all,
                                          const float* __restrict__ bias_all,
                                          char* smx) {
    int*    sSlot = (int*)smx;
    float*  sBias = (float*)(smx + 512);
    char*   sData = smx + 1024;

    const int cnt  = g_count[z];
    const int row0 = by * 128;
    if (row0 >= cnt) return;
    const int jn0  = bx * 128;
    const int tid  = threadIdx.x;
    const int lane = tid & 31;
    const int wid  = tid >> 5;

    if (tid < 128) {
        int r = row0 + tid;
        sSlot[tid] = (r < cnt) ? g_slots[z * T_ + r] : -1;
        sBias[tid] = bias_all[(size_t)z * NDIM + jn0 + tid];
    }

    if (!FIRST) {
        // wait for all 12 G1 n-blocks of (z, by) to finish writing g_hh
        if (tid == 0) {
            volatile int* flag = &g_done[z * 64 + by];
            while (*flag < 12) __nanosleep(64);
        }
    }
    __syncthreads();
    if (!FIRST) __threadfence();   // order subsequent reads after flag observation

    const __half* Abase = FIRST ? g_xh : g_hh;
    const __half* WT    = WT_all + (size_t)z * NDIM * KDIM;

    const uint32_t smb = smem_u32(sData);

    const __half* aSrc[4]; const __half* bSrc[4];
    uint32_t aSz[4], aDst[4], bDst[4];
#pragma unroll
    for (int j = 0; j < 4; j++) {
        int c = tid * 4 + j;
        int row = c >> 3, col = c & 7;
        int slot = sSlot[row];
        int arow = 0; uint32_t sz = 0;
        if (slot >= 0) { arow = FIRST ? (slot >> 1) : slot; sz = 16; }
        aSrc[j] = Abase + (size_t)arow * KDIM + col * 8;
        aSz[j]  = sz;
        bSrc[j] = WT + (size_t)(jn0 + row) * KDIM + col * 8;
        uint32_t o = (uint32_t)(row * 144 + col * 16);
        aDst[j] = smb + o;
        bDst[j] = smb + OP_WORDS * 4 + o;
    }

    constexpr int NC = KDIM / BKH;

#pragma unroll
    for (int st = 0; st < 2; st++) {
        uint32_t so = (uint32_t)(st * STAGE_B);
        const int k0 = st * BKH;
#pragma unroll
        for (int j = 0; j < 4; j++) {
            cp16z(aDst[j] + so, aSrc[j] + k0, aSz[j]);
            cp16 (bDst[j] + so, bSrc[j] + k0);
        }
        CP_COMMIT();
    }

    float acc[4][4][4];
#pragma unroll
    for (int mt = 0; mt < 4; mt++)
#pragma unroll
        for (int nt = 0; nt < 4; nt++)
#pragma unroll
            for (int q = 0; q < 4; q++) acc[mt][nt][q] = 0.f;

    const int warp_m = wid & 1;
    const int warp_n = wid >> 1;
    const int lr = lane >> 2;
    const int lc = lane & 3;

    int awBase[4], bwBase[4];
#pragma unroll
    for (int mt = 0; mt < 4; mt++)
        awBase[mt] = (warp_m * 64 + mt * 16 + lr) * 36 + lc;
#pragma unroll
    for (int nt = 0; nt < 4; nt++)
        bwBase[nt] = (warp_n * 32 + nt * 8 + lr) * 36 + lc;

    int stage = 0;
    for (int kc = 0; kc < NC; kc++) {
        if (kc + 1 < NC) { CP_WAIT1(); } else { CP_WAIT0(); }
        __syncthreads();

        if (kc + 2 < NC) {
            int st2 = stage + 2; if (st2 >= NSTAGE) st2 -= NSTAGE;
            uint32_t so = (uint32_t)(st2 * STAGE_B);
            const int k0 = (kc + 2) * BKH;
#pragma unroll
            for (int j = 0; j < 4; j++) {
                cp16z(aDst[j] + so, aSrc[j] + k0, aSz[j]);
                cp16 (bDst[j] + so, bSrc[j] + k0);
            }
            CP_COMMIT();
        }

        const uint32_t* As32 = (const uint32_t*)(sData + stage * STAGE_B);
        const uint32_t* Bs32 = As32 + OP_WORDS;

#pragma unroll
        for (int s = 0; s < 4; s++) {
            const int sk = s * 8;
            uint32_t afr[4][4];
#pragma unroll
            for (int mt = 0; mt < 4; mt++) {
                int w = awBase[mt] + sk;
                afr[mt][0] = As32[w];
                afr[mt][1] = As32[w + 8 * 36];
                afr[mt][2] = As32[w + 4];
                afr[mt][3] = As32[w + 8 * 36 + 4];
            }
            uint32_t bfr[4][2];
#pragma unroll
            for (int nt = 0; nt < 4; nt++) {
                int w = bwBase[nt] + sk;
                bfr[nt][0] = Bs32[w];
                bfr[nt][1] = Bs32[w + 4];
            }
#pragma unroll
            for (int mt = 0; mt < 4; mt++)
#pragma unroll
                for (int nt = 0; nt < 4; nt++)
                    mma_f16(acc[mt][nt], afr[mt], bfr[nt]);
        }

        stage++; if (stage >= NSTAGE) stage -= NSTAGE;
    }

    // epilogue: bias + (gelu) -> fp16 scatter
#pragma unroll
    for (int mt = 0; mt < 4; mt++) {
        const int rb = warp_m * 64 + mt * 16 + lr;
#pragma unroll
        for (int half_i = 0; half_i < 2; half_i++) {
            int r    = rb + half_i * 8;
            int slot = sSlot[r];
            if (slot < 0) continue;
#pragma unroll
            for (int nt = 0; nt < 4; nt++) {
                int cidx = warp_n * 32 + nt * 8 + 2 * lc;
                float v0 = acc[mt][nt][half_i * 2 + 0] + sBias[cidx];
                float v1 = acc[mt][nt][half_i * 2 + 1] + sBias[cidx + 1];
                if (FIRST) {
                    __half2 hv = __floats2half2_rn(gelu_erf(v0), gelu_erf(v1));
                    *(__half2*)(g_hh + (size_t)slot * NDIM + jn0 + cidx) = hv;
                } else {
                    __half2 hv = __floats2half2_rn(v0, v1);
                    *(__half2*)(g_yh + (size_t)slot * NDIM + jn0 + cidx) = hv;
                }
            }
        }
    }

    if (FIRST) {
        // make g_hh stores visible, then signal completion (threadFence pattern)
        __threadfence();
        __syncthreads();
        if (tid == 0) atomicAdd(&g_done[z * 64 + by], 1);
    }
}

// ---------------------------------------------------------------------------
// Persistent fused GEMM: 296 CTAs pull tile tickets. Tickets [0, NT_G1) are
// GEMM1 tiles, [NT_G1, NT_TOTAL) are GEMM2 tiles (spin on g_done).
#define NT_G1    (X_ * 64 * 12)          // 6144
#define NT_G2    (X_ * 64 * 8)           // 4096
#define NT_TOTAL (NT_G1 + NT_G2)
#define PERSIST_CTAS 296

__global__ __launch_bounds__(256)
void moe_gemm_fused(const __half* __restrict__ w1t, const float* __restrict__ b1,
                    const __half* __restrict__ w2t, const float* __restrict__ b2) {
    extern __shared__ char smx[];
    __shared__ int ts;

    for (;;) {
        __syncthreads();                       // protect ts + smem reuse
        if (threadIdx.x == 0) ts = atomicAdd(&g_ticket, 1);
        __syncthreads();
        const int t = ts;
        if (t >= NT_TOTAL) return;

        if (t < NT_G1) {
            const int z   = t / 768;
            const int rem = t - z * 768;
            gemm_tile<E_, H_, true >(z, rem / 12, rem % 12, w1t, b1, smx);
        } else {
            const int u   = t - NT_G1;
            const int z   = u / 512;
            const int rem = u - z * 512;
            gemm_tile<H_, E_, false>(z, rem / 8, rem % 8, w2t, b2, smx);
        }
    }
}

// ---------------------------------------------------------------------------
// out[t,e] = 0.5*(y[2t,e]+y[2t+1,e]); block 0 re-zeroes scheduler state.
__global__ void reduce_kernel(float* __restrict__ out) {
    if (blockIdx.x == 0) {
        if (threadIdx.x < X_) g_count[threadIdx.x] = 0;
        if (threadIdx.x == X_) g_ticket = 0;
        if (threadIdx.x < 256) { g_done[threadIdx.x] = 0; g_done[threadIdx.x + 256] = 0; }
    }
    int i = blockIdx.x * blockDim.x + threadIdx.x;
    if (i >= T_ * (E_ / 8)) return;
    int t  = i / (E_ / 8);
    int e8 = i - t * (E_ / 8);
    const __half2* ya = (const __half2*)(g_yh + (size_t)(2 * t)     * E_) + e8 * 4;
    const __half2* yb = (const __half2*)(g_yh + (size_t)(2 * t + 1) * E_) + e8 * 4;
    float4 r0, r1;
#pragma unroll
    for (int q = 0; q < 4; q++) {
        float2 a = __half22float2(ya[q]);
        float2 b = __half22float2(yb[q]);
        float rx = 0.5f * (a.x + b.x);
        float ry = 0.5f * (a.y + b.y);
        if (q == 0) { r0.x = rx; r0.y = ry; }
        else if (q == 1) { r0.z = rx; r0.w = ry; }
        else if (q == 2) { r1.x = rx; r1.y = ry; }
        else { r1.z = rx; r1.w = ry; }
    }
    float4* o = (float4*)(out + (size_t)t * E_ + e8 * 8);
    o[0] = r0; o[1] = r1;
}

// ---------------------------------------------------------------------------
extern "C" void kernel_launch(void* const* d_in, const int* in_sizes, int n_in,
                              void* d_out, int out_size) {
    const float* x  = (const float*)d_in[0];
    const float* Wr = (const float*)d_in[1];
    const float* br = (const float*)d_in[2];
    const float* W1 = (const float*)d_in[3];
    const float* b1 = (const float*)d_in[4];
    const float* W2 = (const float*)d_in[5];
    const float* b2 = (const float*)d_in[6];
    float* out = (float*)d_out;

    float* idx_out = (out_size >= (int)((size_t)T_ * E_ + T_ * K_))
                         ? out + (size_t)T_ * E_ : nullptr;

    static __half* w1t_arg = nullptr;
    static __half* w2t_arg = nullptr;
    if (!w1t_arg) {
        cudaGetSymbolAddress((void**)&w1t_arg, g_W1T);
        cudaGetSymbolAddress((void**)&w2t_arg, g_W2T);
        cudaFuncSetAttribute(moe_gemm_fused,
                             cudaFuncAttributeMaxDynamicSharedMemorySize, GEMM_SMEM);
    }

    prep_kernel<<<PREP_TOTAL, 256>>>(x, Wr, br, idx_out, W1, W2);

    moe_gemm_fused<<<PERSIST_CTAS, 256, GEMM_SMEM>>>(w1t_arg, b1, w2t_arg, b2);

    reduce_kernel<<<(T_ * (E_ / 8) + 255) / 256, 256>>>(out);
}

// round 14
// speedup vs baseline: 1.0054x; 1.0054x over previous
#include <cuda_runtime.h>
#include <cuda_fp16.h>
#include <math.h>
#include <stdint.h>

// MoE: B=8, N=1024, E=1024, H=1536, X=8, K=2
#define B_  8
#define N_  1024
#define T_  (B_*N_)      // 8192 tokens
#define E_  1024
#define H_  1536
#define X_  8
#define K_  2
#define TS_ (T_*K_)      // 16384 (token, slot) pairs

// ---- scratch (allocation-free: __device__ globals; g_count zero-init at
//      load, re-zeroed by reduce_kernel each launch) ----
__device__ int    g_count[X_];
__device__ int    g_slots[X_ * T_];                      // slot id = t*K + k
__device__ __half g_xh[(size_t)T_ * E_];                 // x in fp16
__device__ __half g_W1T[(size_t)X_ * H_ * E_];           // [x][h][e] fp16 (B n-major)
__device__ __half g_W2T[(size_t)X_ * E_ * H_];           // [x][e][h] fp16
__device__ __half g_hh[(size_t)TS_ * H_];                // post-GELU hidden (fp16)
__device__ __half g_yh[(size_t)TS_ * E_];                // expert output (fp16)

// ============================ helpers =======================================
__device__ __forceinline__ uint32_t smem_u32(const void* p) {
    uint32_t a;
    asm("{ .reg .u64 t; cvta.to.shared.u64 t, %1; cvt.u32.u64 %0, t; }" : "=r"(a) : "l"(p));
    return a;
}
__device__ __forceinline__ void cp16z(uint32_t dst, const void* src, uint32_t sz) {
    asm volatile("cp.async.cg.shared.global [%0], [%1], 16, %2;"
                 :: "r"(dst), "l"(src), "r"(sz) : "memory");
}
__device__ __forceinline__ void cp16(uint32_t dst, const void* src) {
    asm volatile("cp.async.cg.shared.global [%0], [%1], 16;"
                 :: "r"(dst), "l"(src) : "memory");
}
#define CP_COMMIT() asm volatile("cp.async.commit_group;" ::: "memory")
#define CP_WAIT0()  asm volatile("cp.async.wait_group 0;" ::: "memory")
#define CP_WAIT1()  asm volatile("cp.async.wait_group 1;" ::: "memory")

__device__ __forceinline__ void mma_f16(float* c, const uint32_t* a, const uint32_t* b) {
    asm volatile("mma.sync.aligned.m16n8k16.row.col.f32.f16.f16.f32 "
                 "{%0,%1,%2,%3}, {%4,%5,%6,%7}, {%8,%9}, {%0,%1,%2,%3};"
                 : "+f"(c[0]), "+f"(c[1]), "+f"(c[2]), "+f"(c[3])
                 : "r"(a[0]), "r"(a[1]), "r"(a[2]), "r"(a[3]), "r"(b[0]), "r"(b[1]));
}

__device__ __forceinline__ float gelu_erf(float v) {
    return 0.5f * v * (1.0f + erff(v * 0.70710678118654752f));
}

// ---------------------------------------------------------------------------
// Fused prep kernel: block-partitioned roles (router+cvt | W1 T | W2 T).
// Transpose uses a float2-packed tile: both LDS phases conflict-free.
#define PREP_RTR    (T_ / 8)                  // 1024
#define PREP_TPB    768
#define PREP_W1     PREP_RTR
#define PREP_W2     (PREP_RTR + PREP_TPB * X_)
#define PREP_TOTAL  (PREP_RTR + 2 * PREP_TPB * X_)

__device__ __forceinline__ void transpose_body(
    const float* __restrict__ in, __half* __restrict__ out,
    int R, int C, int z, int cb, int rb, float2 (*t2)[33], int tid) {
    size_t base = (size_t)z * R * C;
    in  += base; out += base;
    const int c0 = cb * 32, r0 = rb * 64;
    const int tx = tid & 31, ty = tid >> 5;    // 32 x 8
    // load row-pairs: t2[rp][c] = (in[2rp][c], in[2rp+1][c]); coalesced reads
#pragma unroll
    for (int j = 0; j < 32; j += 8) {
        int rp = ty + j;                       // 0..31
        float a = in[(size_t)(r0 + 2 * rp)     * C + c0 + tx];
        float b = in[(size_t)(r0 + 2 * rp + 1) * C + c0 + tx];
        t2[rp][tx] = make_float2(a, b);
    }
    __syncthreads();
    // store: one LDS.64 per half2 output; conflict-free per 16-thread phase
#pragma unroll
    for (int j = 0; j < 32; j += 8) {
        int c = ty + j;
        float2 v = t2[tx][c];
        *(__half2*)(out + (size_t)(c0 + c) * R + r0 + 2 * tx) =
            __floats2half2_rn(v.x, v.y);
    }
}

__global__ __launch_bounds__(256)
void prep_kernel(const float* __restrict__ x,
                 const float* __restrict__ Wr,
                 const float* __restrict__ br,
                 float* __restrict__ out_idx,
                 const float* __restrict__ W1,
                 const float* __restrict__ W2) {
    __shared__ float2 t2[32][33];
    const int bx  = blockIdx.x;
    const int tid = threadIdx.x;

    if (bx >= PREP_RTR) {
        int idx, R, C;
        const float* in; __half* out;
        if (bx < PREP_W2) { idx = bx - PREP_W1; in = W1; out = g_W1T; R = E_; C = H_; }
        else              { idx = bx - PREP_W2; in = W2; out = g_W2T; R = H_; C = E_; }
        const int cbn = C / 32;
        const int z   = idx / PREP_TPB;
        const int rem = idx - z * PREP_TPB;
        const int rb  = rem / cbn;
        const int cb  = rem - rb * cbn;
        transpose_body(in, out, R, C, z, cb, rb, t2, tid);
        return;
    }

    // router role: warp w handles token bx*8 + w. Requires g_count==0 on entry.
    const int gwarp = bx * 8 + (tid >> 5);
    const int lane  = tid & 31;
    const float* xr = x + (size_t)gwarp * E_;
    __half* xh = g_xh + (size_t)gwarp * E_;

    float acc[X_];
#pragma unroll
    for (int j = 0; j < X_; j++) acc[j] = 0.f;
    for (int e = lane * 2; e < E_; e += 64) {
        float2 xv = *(const float2*)(xr + e);
        *(__half2*)(xh + e) = __floats2half2_rn(xv.x, xv.y);
#pragma unroll
        for (int rep = 0; rep < 2; rep++) {
            float v = rep ? xv.y : xv.x;
            const float4* w4 = (const float4*)(Wr + (size_t)(e + rep) * X_);
            float4 w0 = w4[0], w1 = w4[1];
            acc[0] += v * w0.x; acc[1] += v * w0.y;
            acc[2] += v * w0.z; acc[3] += v * w0.w;
            acc[4] += v * w1.x; acc[5] += v * w1.y;
            acc[6] += v * w1.z; acc[7] += v * w1.w;
        }
    }
#pragma unroll
    for (int j = 0; j < X_; j++)
#pragma unroll
        for (int off = 16; off > 0; off >>= 1)
            acc[j] += __shfl_down_sync(0xffffffffu, acc[j], off);

    if (lane == 0) {
        float v0 = -3.0e38f, v1 = -3.0e38f;
        int   i0 = 0,        i1 = 0;
#pragma unroll
        for (int j = 0; j < X_; j++) {
            float v = acc[j] + br[j];
            if (v > v0)      { v1 = v0; i1 = i0; v0 = v; i0 = j; }
            else if (v > v1) { v1 = v;  i1 = j; }
        }
        if (out_idx) {
            out_idx[gwarp * K_ + 0] = (float)i0;
            out_idx[gwarp * K_ + 1] = (float)i1;
        }
        int p0 = atomicAdd(&g_count[i0], 1);
        g_slots[i0 * T_ + p0] = gwarp * K_ + 0;
        int p1 = atomicAdd(&g_count[i1], 1);
        g_slots[i1 * T_ + p1] = gwarp * K_ + 1;
    }
}

// ---------------------------------------------------------------------------
// fp16 mma.sync grouped GEMM: 128x128 tile, 256 threads (8 warps, 2x4 grid of
// 64x32 warp tiles), BK=64, 3-stage cp.async ring, scalar-LDS fragments.
// FIRST: C = gelu(xh[token] @ W1T^T + b1) -> g_hh  (KDIM=E_, NDIM=H_)
// else : C =      g_hh[slot] @ W2T^T + b2 -> g_yh  (KDIM=H_, NDIM=E_, fp16)
#define BKH      64
#define OP_WORDS (128 * 36)
#define STAGE_B  (2 * OP_WORDS * 4)
#define NSTAGE   3
#define GEMM_SMEM (1024 + NSTAGE * STAGE_B)

template<int KDIM, int NDIM, bool FIRST>
__global__ __launch_bounds__(256)
void expert_gemm_h(const __half* __restrict__ WT_all,
                   const float* __restrict__ bias_all) {
    extern __shared__ char smx[];
    int*    sSlot = (int*)smx;
    float*  sBias = (float*)(smx + 512);
    char*   sData = smx + 1024;

    const int z    = blockIdx.z;
    const int cnt  = g_count[z];
    const int row0 = blockIdx.y * 128;
    if (row0 >= cnt) return;
    const int jn0  = blockIdx.x * 128;
    const int tid  = threadIdx.x;
    const int lane = tid & 31;
    const int wid  = tid >> 5;

    if (tid < 128) {
        int r = row0 + tid;
        sSlot[tid] = (r < cnt) ? g_slots[z * T_ + r] : -1;
        sBias[tid] = bias_all[(size_t)z * NDIM + jn0 + tid];
    }
    __syncthreads();

    const __half* Abase = FIRST ? g_xh : g_hh;
    const __half* WT    = WT_all + (size_t)z * NDIM * KDIM;

    const uint32_t smb = smem_u32(sData);

    const __half* aSrc[4]; const __half* bSrc[4];
    uint32_t aSz[4], aDst[4], bDst[4];
#pragma unroll
    for (int j = 0; j < 4; j++) {
        int c = tid * 4 + j;
        int row = c >> 3, col = c & 7;
        int slot = sSlot[row];
        int arow = 0; uint32_t sz = 0;
        if (slot >= 0) { arow = FIRST ? (slot >> 1) : slot; sz = 16; }
        aSrc[j] = Abase + (size_t)arow * KDIM + col * 8;
        aSz[j]  = sz;
        bSrc[j] = WT + (size_t)(jn0 + row) * KDIM + col * 8;
        uint32_t o = (uint32_t)(row * 144 + col * 16);
        aDst[j] = smb + o;
        bDst[j] = smb + OP_WORDS * 4 + o;
    }

    constexpr int NC = KDIM / BKH;

#pragma unroll
    for (int st = 0; st < 2; st++) {
        uint32_t so = (uint32_t)(st * STAGE_B);
        const int k0 = st * BKH;
#pragma unroll
        for (int j = 0; j < 4; j++) {
            cp16z(aDst[j] + so, aSrc[j] + k0, aSz[j]);
            cp16 (bDst[j] + so, bSrc[j] + k0);
        }
        CP_COMMIT();
    }

    float acc[4][4][4];
#pragma unroll
    for (int mt = 0; mt < 4; mt++)
#pragma unroll
        for (int nt = 0; nt < 4; nt++)
#pragma unroll
            for (int q = 0; q < 4; q++) acc[mt][nt][q] = 0.f;

    const int warp_m = wid & 1;
    const int warp_n = wid >> 1;
    const int lr = lane >> 2;
    const int lc = lane & 3;

    int awBase[4], bwBase[4];
#pragma unroll
    for (int mt = 0; mt < 4; mt++)
        awBase[mt] = (warp_m * 64 + mt * 16 + lr) * 36 + lc;
#pragma unroll
    for (int nt = 0; nt < 4; nt++)
        bwBase[nt] = (warp_n * 32 + nt * 8 + lr) * 36 + lc;

    int stage = 0;
    for (int kc = 0; kc < NC; kc++) {
        if (kc + 1 < NC) { CP_WAIT1(); } else { CP_WAIT0(); }
        __syncthreads();

        if (kc + 2 < NC) {
            int st2 = stage + 2; if (st2 >= NSTAGE) st2 -= NSTAGE;
            uint32_t so = (uint32_t)(st2 * STAGE_B);
            const int k0 = (kc + 2) * BKH;
#pragma unroll
            for (int j = 0; j < 4; j++) {
                cp16z(aDst[j] + so, aSrc[j] + k0, aSz[j]);
                cp16 (bDst[j] + so, bSrc[j] + k0);
            }
            CP_COMMIT();
        }

        const uint32_t* As32 = (const uint32_t*)(sData + stage * STAGE_B);
        const uint32_t* Bs32 = As32 + OP_WORDS;

#pragma unroll
        for (int s = 0; s < 4; s++) {
            const int sk = s * 8;
            uint32_t afr[4][4];
#pragma unroll
            for (int mt = 0; mt < 4; mt++) {
                int w = awBase[mt] + sk;
                afr[mt][0] = As32[w];
                afr[mt][1] = As32[w + 8 * 36];
                afr[mt][2] = As32[w + 4];
                afr[mt][3] = As32[w + 8 * 36 + 4];
            }
            uint32_t bfr[4][2];
#pragma unroll
            for (int nt = 0; nt < 4; nt++) {
                int w = bwBase[nt] + sk;
                bfr[nt][0] = Bs32[w];
                bfr[nt][1] = Bs32[w + 4];
            }
#pragma unroll
            for (int mt = 0; mt < 4; mt++)
#pragma unroll
                for (int nt = 0; nt < 4; nt++)
                    mma_f16(acc[mt][nt], afr[mt], bfr[nt]);
        }

        stage++; if (stage >= NSTAGE) stage -= NSTAGE;
    }

    // epilogue: bias + (gelu) -> fp16 scatter
#pragma unroll
    for (int mt = 0; mt < 4; mt++) {
        const int rb = warp_m * 64 + mt * 16 + lr;
#pragma unroll
        for (int half_i = 0; half_i < 2; half_i++) {
            int r    = rb + half_i * 8;
            int slot = sSlot[r];
            if (slot < 0) continue;
#pragma unroll
            for (int nt = 0; nt < 4; nt++) {
                int cidx = warp_n * 32 + nt * 8 + 2 * lc;
                float v0 = acc[mt][nt][half_i * 2 + 0] + sBias[cidx];
                float v1 = acc[mt][nt][half_i * 2 + 1] + sBias[cidx + 1];
                if (FIRST) {
                    __half2 hv = __floats2half2_rn(gelu_erf(v0), gelu_erf(v1));
                    *(__half2*)(g_hh + (size_t)slot * NDIM + jn0 + cidx) = hv;
                } else {
                    __half2 hv = __floats2half2_rn(v0, v1);
                    *(__half2*)(g_yh + (size_t)slot * NDIM + jn0 + cidx) = hv;
                }
            }
        }
    }
}

// ---------------------------------------------------------------------------
// One block per token: out[t,e] = 0.5*(y[2t,e]+y[2t+1,e]). 128 threads, each
// handles 8 elements (4 half2 loads, 2 float4 stores). Block 0 re-zeroes
// g_count (first launch relies on load-time zero-init).
__global__ __launch_bounds__(128)
void reduce_kernel(float* __restrict__ out) {
    const int t   = blockIdx.x;
    const int tid = threadIdx.x;
    if (t == 0 && tid < X_) g_count[tid] = 0;
    const __half2* ya = (const __half2*)(g_yh + (size_t)(2 * t)     * E_) + tid * 4;
    const __half2* yb = (const __half2*)(g_yh + (size_t)(2 * t + 1) * E_) + tid * 4;
    float4 r0, r1;
#pragma unroll
    for (int q = 0; q < 4; q++) {
        float2 a = __half22float2(ya[q]);
        float2 b = __half22float2(yb[q]);
        float rx = 0.5f * (a.x + b.x);
        float ry = 0.5f * (a.y + b.y);
        if (q == 0) { r0.x = rx; r0.y = ry; }
        else if (q == 1) { r0.z = rx; r0.w = ry; }
        else if (q == 2) { r1.x = rx; r1.y = ry; }
        else { r1.z = rx; r1.w = ry; }
    }
    float4* o = (float4*)(out + (size_t)t * E_ + tid * 8);
    o[0] = r0; o[1] = r1;
}

// ---------------------------------------------------------------------------
extern "C" void kernel_launch(void* const* d_in, const int* in_sizes, int n_in,
                              void* d_out, int out_size) {
    const float* x  = (const float*)d_in[0];
    const float* Wr = (const float*)d_in[1];
    const float* br = (const float*)d_in[2];
    const float* W1 = (const float*)d_in[3];
    const float* b1 = (const float*)d_in[4];
    const float* W2 = (const float*)d_in[5];
    const float* b2 = (const float*)d_in[6];
    float* out = (float*)d_out;

    float* idx_out = (out_size >= (int)((size_t)T_ * E_ + T_ * K_))
                         ? out + (size_t)T_ * E_ : nullptr;

    static __half* w1t_arg = nullptr;
    static __half* w2t_arg = nullptr;
    if (!w1t_arg) {
        cudaGetSymbolAddress((void**)&w1t_arg, g_W1T);
        cudaGetSymbolAddress((void**)&w2t_arg, g_W2T);
        cudaFuncSetAttribute(expert_gemm_h<E_, H_, true>,
                             cudaFuncAttributeMaxDynamicSharedMemorySize, GEMM_SMEM);
        cudaFuncSetAttribute(expert_gemm_h<H_, E_, false>,
                             cudaFuncAttributeMaxDynamicSharedMemorySize, GEMM_SMEM);
    }

    prep_kernel<<<PREP_TOTAL, 256>>>(x, Wr, br, idx_out, W1, W2);

    expert_gemm_h<E_, H_, true ><<<dim3(H_ / 128, T_ / 128, X_), 256, GEMM_SMEM>>>(w1t_arg, b1);
    expert_gemm_h<H_, E_, false><<<dim3(E_ / 128, T_ / 128, X_), 256, GEMM_SMEM>>>(w2t_arg, b2);

    reduce_kernel<<<T_, 128>>>(out);
}

// round 15
// speedup vs baseline: 1.0262x; 1.0206x over previous
#include <cuda_runtime.h>
#include <cuda_fp16.h>
#include <math.h>
#include <stdint.h>

// MoE: B=8, N=1024, E=1024, H=1536, X=8, K=2
#define B_  8
#define N_  1024
#define T_  (B_*N_)      // 8192 tokens
#define E_  1024
#define H_  1536
#define X_  8
#define K_  2
#define TS_ (T_*K_)      // 16384 (token, slot) pairs

// ---- scratch (allocation-free: __device__ globals; g_count zero-init at
//      load, re-zeroed by reduce_kernel each launch) ----
__device__ int    g_count[X_];
__device__ int    g_slots[X_ * T_];                      // slot id = t*K + k
__device__ __half g_xh[(size_t)T_ * E_];                 // x in fp16
__device__ __half g_W1T[(size_t)X_ * H_ * E_];           // [x][h][e] fp16 (B n-major)
__device__ __half g_W2T[(size_t)X_ * E_ * H_];           // [x][e][h] fp16
__device__ __half g_hh[(size_t)TS_ * H_];                // post-GELU hidden (fp16)
__device__ __half g_yh[(size_t)TS_ * E_];                // expert output (fp16)

// ============================ helpers =======================================
__device__ __forceinline__ uint32_t smem_u32(const void* p) {
    uint32_t a;
    asm("{ .reg .u64 t; cvta.to.shared.u64 t, %1; cvt.u32.u64 %0, t; }" : "=r"(a) : "l"(p));
    return a;
}
__device__ __forceinline__ void cp16z(uint32_t dst, const void* src, uint32_t sz) {
    asm volatile("cp.async.cg.shared.global [%0], [%1], 16, %2;"
                 :: "r"(dst), "l"(src), "r"(sz) : "memory");
}
__device__ __forceinline__ void cp16(uint32_t dst, const void* src) {
    asm volatile("cp.async.cg.shared.global [%0], [%1], 16;"
                 :: "r"(dst), "l"(src) : "memory");
}
#define CP_COMMIT() asm volatile("cp.async.commit_group;" ::: "memory")
#define CP_WAIT0()  asm volatile("cp.async.wait_group 0;" ::: "memory")
#define CP_WAIT1()  asm volatile("cp.async.wait_group 1;" ::: "memory")

__device__ __forceinline__ void mma_f16(float* c, const uint32_t* a, const uint32_t* b) {
    asm volatile("mma.sync.aligned.m16n8k16.row.col.f32.f16.f16.f32 "
                 "{%0,%1,%2,%3}, {%4,%5,%6,%7}, {%8,%9}, {%0,%1,%2,%3};"
                 : "+f"(c[0]), "+f"(c[1]), "+f"(c[2]), "+f"(c[3])
                 : "r"(a[0]), "r"(a[1]), "r"(a[2]), "r"(a[3]), "r"(b[0]), "r"(b[1]));
}

__device__ __forceinline__ float gelu_erf(float v) {
    return 0.5f * v * (1.0f + erff(v * 0.70710678118654752f));
}

// ---------------------------------------------------------------------------
// Fused prep kernel: block-partitioned roles (router+cvt | W1 T | W2 T).
// Router blocks cache Wr TRANSPOSED in smem (sW[j][e]) -- read once per block
// instead of once per warp (kills ~256MB of redundant L2 traffic).
#define PREP_RTR    (T_ / 8)                  // 1024
#define PREP_TPB    768
#define PREP_W1     PREP_RTR
#define PREP_W2     (PREP_RTR + PREP_TPB * X_)
#define PREP_TOTAL  (PREP_RTR + 2 * PREP_TPB * X_)

__device__ __forceinline__ void transpose_body(
    const float* __restrict__ in, __half* __restrict__ out,
    int R, int C, int z, int cb, int rb, float2 (*t2)[33], int tid) {
    size_t base = (size_t)z * R * C;
    in  += base; out += base;
    const int c0 = cb * 32, r0 = rb * 64;
    const int tx = tid & 31, ty = tid >> 5;    // 32 x 8
#pragma unroll
    for (int j = 0; j < 32; j += 8) {
        int rp = ty + j;                       // 0..31
        float a = in[(size_t)(r0 + 2 * rp)     * C + c0 + tx];
        float b = in[(size_t)(r0 + 2 * rp + 1) * C + c0 + tx];
        t2[rp][tx] = make_float2(a, b);
    }
    __syncthreads();
#pragma unroll
    for (int j = 0; j < 32; j += 8) {
        int c = ty + j;
        float2 v = t2[tx][c];
        *(__half2*)(out + (size_t)(c0 + c) * R + r0 + 2 * tx) =
            __floats2half2_rn(v.x, v.y);
    }
}

__global__ __launch_bounds__(256)
void prep_kernel(const float* __restrict__ x,
                 const float* __restrict__ Wr,
                 const float* __restrict__ br,
                 float* __restrict__ out_idx,
                 const float* __restrict__ W1,
                 const float* __restrict__ W2) {
    __shared__ union {
        float2 t2[32][33];            // transpose tile (8448 B)
        float  sW[X_][E_];            // router: Wr transposed (32 KB)
    } sm;
    const int bx  = blockIdx.x;
    const int tid = threadIdx.x;

    if (bx >= PREP_RTR) {
        int idx, R, C;
        const float* in; __half* out;
        if (bx < PREP_W2) { idx = bx - PREP_W1; in = W1; out = g_W1T; R = E_; C = H_; }
        else              { idx = bx - PREP_W2; in = W2; out = g_W2T; R = H_; C = E_; }
        const int cbn = C / 32;
        const int z   = idx / PREP_TPB;
        const int rem = idx - z * PREP_TPB;
        const int rb  = rem / cbn;
        const int cb  = rem - rb * cbn;
        transpose_body(in, out, R, C, z, cb, rb, sm.t2, tid);
        return;
    }

    // router role: stage Wr transposed into smem (cooperative, once per block)
    for (int e = tid; e < E_; e += 256) {
        const float4* w4 = (const float4*)(Wr + (size_t)e * X_);
        float4 w0 = w4[0], w1 = w4[1];
        sm.sW[0][e] = w0.x; sm.sW[1][e] = w0.y;
        sm.sW[2][e] = w0.z; sm.sW[3][e] = w0.w;
        sm.sW[4][e] = w1.x; sm.sW[5][e] = w1.y;
        sm.sW[6][e] = w1.z; sm.sW[7][e] = w1.w;
    }
    __syncthreads();

    // warp w handles token bx*8 + w. Requires g_count==0 on entry.
    const int gwarp = bx * 8 + (tid >> 5);
    const int lane  = tid & 31;
    const float* xr = x + (size_t)gwarp * E_;
    __half* xh = g_xh + (size_t)gwarp * E_;

    float acc[X_];
#pragma unroll
    for (int j = 0; j < X_; j++) acc[j] = 0.f;
    for (int e = lane; e < E_; e += 32) {
        float v = xr[e];
        xh[e] = __float2half_rn(v);
#pragma unroll
        for (int j = 0; j < X_; j++) acc[j] += v * sm.sW[j][e];
    }
#pragma unroll
    for (int j = 0; j < X_; j++)
#pragma unroll
        for (int off = 16; off > 0; off >>= 1)
            acc[j] += __shfl_down_sync(0xffffffffu, acc[j], off);

    if (lane == 0) {
        float v0 = -3.0e38f, v1 = -3.0e38f;
        int   i0 = 0,        i1 = 0;
#pragma unroll
        for (int j = 0; j < X_; j++) {
            float v = acc[j] + br[j];
            if (v > v0)      { v1 = v0; i1 = i0; v0 = v; i0 = j; }
            else if (v > v1) { v1 = v;  i1 = j; }
        }
        if (out_idx) {
            out_idx[gwarp * K_ + 0] = (float)i0;
            out_idx[gwarp * K_ + 1] = (float)i1;
        }
        int p0 = atomicAdd(&g_count[i0], 1);
        g_slots[i0 * T_ + p0] = gwarp * K_ + 0;
        int p1 = atomicAdd(&g_count[i1], 1);
        g_slots[i1 * T_ + p1] = gwarp * K_ + 1;
    }
}

// ---------------------------------------------------------------------------
// fp16 mma.sync grouped GEMM: 128x128 tile, 256 threads (8 warps, 2x4 grid of
// 64x32 warp tiles), BK=64, 3-stage cp.async ring, scalar-LDS fragments.
// FIRST: C = gelu(xh[token] @ W1T^T + b1) -> g_hh  (KDIM=E_, NDIM=H_)
// else : C =      g_hh[slot] @ W2T^T + b2 -> g_yh  (KDIM=H_, NDIM=E_, fp16)
#define BKH      64
#define OP_WORDS (128 * 36)
#define STAGE_B  (2 * OP_WORDS * 4)
#define NSTAGE   3
#define GEMM_SMEM (1024 + NSTAGE * STAGE_B)

template<int KDIM, int NDIM, bool FIRST>
__global__ __launch_bounds__(256)
void expert_gemm_h(const __half* __restrict__ WT_all,
                   const float* __restrict__ bias_all) {
    extern __shared__ char smx[];
    int*    sSlot = (int*)smx;
    float*  sBias = (float*)(smx + 512);
    char*   sData = smx + 1024;

    const int z    = blockIdx.z;
    const int cnt  = g_count[z];
    const int row0 = blockIdx.y * 128;
    if (row0 >= cnt) return;
    const int jn0  = blockIdx.x * 128;
    const int tid  = threadIdx.x;
    const int lane = tid & 31;
    const int wid  = tid >> 5;

    if (tid < 128) {
        int r = row0 + tid;
        sSlot[tid] = (r < cnt) ? g_slots[z * T_ + r] : -1;
        sBias[tid] = bias_all[(size_t)z * NDIM + jn0 + tid];
    }
    __syncthreads();

    const __half* Abase = FIRST ? g_xh : g_hh;
    const __half* WT    = WT_all + (size_t)z * NDIM * KDIM;

    const uint32_t smb = smem_u32(sData);

    const __half* aSrc[4]; const __half* bSrc[4];
    uint32_t aSz[4], aDst[4], bDst[4];
#pragma unroll
    for (int j = 0; j < 4; j++) {
        int c = tid * 4 + j;
        int row = c >> 3, col = c & 7;
        int slot = sSlot[row];
        int arow = 0; uint32_t sz = 0;
        if (slot >= 0) { arow = FIRST ? (slot >> 1) : slot; sz = 16; }
        aSrc[j] = Abase + (size_t)arow * KDIM + col * 8;
        aSz[j]  = sz;
        bSrc[j] = WT + (size_t)(jn0 + row) * KDIM + col * 8;
        uint32_t o = (uint32_t)(row * 144 + col * 16);
        aDst[j] = smb + o;
        bDst[j] = smb + OP_WORDS * 4 + o;
    }

    constexpr int NC = KDIM / BKH;

#pragma unroll
    for (int st = 0; st < 2; st++) {
        uint32_t so = (uint32_t)(st * STAGE_B);
        const int k0 = st * BKH;
#pragma unroll
        for (int j = 0; j < 4; j++) {
            cp16z(aDst[j] + so, aSrc[j] + k0, aSz[j]);
            cp16 (bDst[j] + so, bSrc[j] + k0);
        }
        CP_COMMIT();
    }

    float acc[4][4][4];
#pragma unroll
    for (int mt = 0; mt < 4; mt++)
#pragma unroll
        for (int nt = 0; nt < 4; nt++)
#pragma unroll
            for (int q = 0; q < 4; q++) acc[mt][nt][q] = 0.f;

    const int warp_m = wid & 1;
    const int warp_n = wid >> 1;
    const int lr = lane >> 2;
    const int lc = lane & 3;

    int awBase[4], bwBase[4];
#pragma unroll
    for (int mt = 0; mt < 4; mt++)
        awBase[mt] = (warp_m * 64 + mt * 16 + lr) * 36 + lc;
#pragma unroll
    for (int nt = 0; nt < 4; nt++)
        bwBase[nt] = (warp_n * 32 + nt * 8 + lr) * 36 + lc;

    int stage = 0;
    for (int kc = 0; kc < NC; kc++) {
        if (kc + 1 < NC) { CP_WAIT1(); } else { CP_WAIT0(); }
        __syncthreads();

        if (kc + 2 < NC) {
            int st2 = stage + 2; if (st2 >= NSTAGE) st2 -= NSTAGE;
            uint32_t so = (uint32_t)(st2 * STAGE_B);
            const int k0 = (kc + 2) * BKH;
#pragma unroll
            for (int j = 0; j < 4; j++) {
                cp16z(aDst[j] + so, aSrc[j] + k0, aSz[j]);
                cp16 (bDst[j] + so, bSrc[j] + k0);
            }
            CP_COMMIT();
        }

        const uint32_t* As32 = (const uint32_t*)(sData + stage * STAGE_B);
        const uint32_t* Bs32 = As32 + OP_WORDS;

#pragma unroll
        for (int s = 0; s < 4; s++) {
            const int sk = s * 8;
            uint32_t afr[4][4];
#pragma unroll
            for (int mt = 0; mt < 4; mt++) {
                int w = awBase[mt] + sk;
                afr[mt][0] = As32[w];
                afr[mt][1] = As32[w + 8 * 36];
                afr[mt][2] = As32[w + 4];
                afr[mt][3] = As32[w + 8 * 36 + 4];
            }
            uint32_t bfr[4][2];
#pragma unroll
            for (int nt = 0; nt < 4; nt++) {
                int w = bwBase[nt] + sk;
                bfr[nt][0] = Bs32[w];
                bfr[nt][1] = Bs32[w + 4];
            }
#pragma unroll
            for (int mt = 0; mt < 4; mt++)
#pragma unroll
                for (int nt = 0; nt < 4; nt++)
                    mma_f16(acc[mt][nt], afr[mt], bfr[nt]);
        }

        stage++; if (stage >= NSTAGE) stage -= NSTAGE;
    }

    // epilogue: bias + (gelu) -> fp16 scatter
#pragma unroll
    for (int mt = 0; mt < 4; mt++) {
        const int rb = warp_m * 64 + mt * 16 + lr;
#pragma unroll
        for (int half_i = 0; half_i < 2; half_i++) {
            int r    = rb + half_i * 8;
            int slot = sSlot[r];
            if (slot < 0) continue;
#pragma unroll
            for (int nt = 0; nt < 4; nt++) {
                int cidx = warp_n * 32 + nt * 8 + 2 * lc;
                float v0 = acc[mt][nt][half_i * 2 + 0] + sBias[cidx];
                float v1 = acc[mt][nt][half_i * 2 + 1] + sBias[cidx + 1];
                if (FIRST) {
                    __half2 hv = __floats2half2_rn(gelu_erf(v0), gelu_erf(v1));
                    *(__half2*)(g_hh + (size_t)slot * NDIM + jn0 + cidx) = hv;
                } else {
                    __half2 hv = __floats2half2_rn(v0, v1);
                    *(__half2*)(g_yh + (size_t)slot * NDIM + jn0 + cidx) = hv;
                }
            }
        }
    }
}

// ---------------------------------------------------------------------------
// One block per token: out[t,e] = 0.5*(y[2t,e]+y[2t+1,e]). Block 0 re-zeroes
// g_count (first launch relies on load-time zero-init).
__global__ __launch_bounds__(128)
void reduce_kernel(float* __restrict__ out) {
    const int t   = blockIdx.x;
    const int tid = threadIdx.x;
    if (t == 0 && tid < X_) g_count[tid] = 0;
    const __half2* ya = (const __half2*)(g_yh + (size_t)(2 * t)     * E_) + tid * 4;
    const __half2* yb = (const __half2*)(g_yh + (size_t)(2 * t + 1) * E_) + tid * 4;
    float4 r0, r1;
#pragma unroll
    for (int q = 0; q < 4; q++) {
        float2 a = __half22float2(ya[q]);
        float2 b = __half22float2(yb[q]);
        float rx = 0.5f * (a.x + b.x);
        float ry = 0.5f * (a.y + b.y);
        if (q == 0) { r0.x = rx; r0.y = ry; }
        else if (q == 1) { r0.z = rx; r0.w = ry; }
        else if (q == 2) { r1.x = rx; r1.y = ry; }
        else { r1.z = rx; r1.w = ry; }
    }
    float4* o = (float4*)(out + (size_t)t * E_ + tid * 8);
    o[0] = r0; o[1] = r1;
}

// ---------------------------------------------------------------------------
extern "C" void kernel_launch(void* const* d_in, const int* in_sizes, int n_in,
                              void* d_out, int out_size) {
    const float* x  = (const float*)d_in[0];
    const float* Wr = (const float*)d_in[1];
    const float* br = (const float*)d_in[2];
    const float* W1 = (const float*)d_in[3];
    const float* b1 = (const float*)d_in[4];
    const float* W2 = (const float*)d_in[5];
    const float* b2 = (const float*)d_in[6];
    float* out = (float*)d_out;

    float* idx_out = (out_size >= (int)((size_t)T_ * E_ + T_ * K_))
                         ? out + (size_t)T_ * E_ : nullptr;

    static __half* w1t_arg = nullptr;
    static __half* w2t_arg = nullptr;
    if (!w1t_arg) {
        cudaGetSymbolAddress((void**)&w1t_arg, g_W1T);
        cudaGetSymbolAddress((void**)&w2t_arg, g_W2T);
        cudaFuncSetAttribute(expert_gemm_h<E_, H_, true>,
                             cudaFuncAttributeMaxDynamicSharedMemorySize, GEMM_SMEM);
        cudaFuncSetAttribute(expert_gemm_h<H_, E_, false>,
                             cudaFuncAttributeMaxDynamicSharedMemorySize, GEMM_SMEM);
    }

    prep_kernel<<<PREP_TOTAL, 256>>>(x, Wr, br, idx_out, W1, W2);

    expert_gemm_h<E_, H_, true ><<<dim3(H_ / 128, T_ / 128, X_), 256, GEMM_SMEM>>>(w1t_arg, b1);
    expert_gemm_h<H_, E_, false><<<dim3(E_ / 128, T_ / 128, X_), 256, GEMM_SMEM>>>(w2t_arg, b2);

    reduce_kernel<<<T_, 128>>>(out);
}

// round 16
// speedup vs baseline: 1.0355x; 1.0091x over previous
#include <cuda_runtime.h>
#include <cuda_fp16.h>
#include <math.h>
#include <stdint.h>

// MoE: B=8, N=1024, E=1024, H=1536, X=8, K=2
#define B_  8
#define N_  1024
#define T_  (B_*N_)      // 8192 tokens
#define E_  1024
#define H_  1536
#define X_  8
#define K_  2
#define TS_ (T_*K_)      // 16384 (token, slot) pairs

// ---- scratch (allocation-free: __device__ globals; zero-init at load,
//      re-zeroed by reduce_kernel each launch) ----
__device__ int    g_count[X_];
__device__ int    g_ticket;                              // W2T worker tickets
__device__ int    g_slots[X_ * T_];                      // slot id = t*K + k
__device__ __half g_xh[(size_t)T_ * E_];                 // x in fp16
__device__ __half g_W1T[(size_t)X_ * H_ * E_];           // [x][h][e] fp16 (B n-major)
__device__ __half g_W2T[(size_t)X_ * E_ * H_];           // [x][e][h] fp16
__device__ __half g_hh[(size_t)TS_ * H_];                // post-GELU hidden (fp16)
__device__ __half g_yh[(size_t)TS_ * E_];                // expert output (fp16)

// ============================ helpers =======================================
__device__ __forceinline__ uint32_t smem_u32(const void* p) {
    uint32_t a;
    asm("{ .reg .u64 t; cvta.to.shared.u64 t, %1; cvt.u32.u64 %0, t; }" : "=r"(a) : "l"(p));
    return a;
}
__device__ __forceinline__ void cp16z(uint32_t dst, const void* src, uint32_t sz) {
    asm volatile("cp.async.cg.shared.global [%0], [%1], 16, %2;"
                 :: "r"(dst), "l"(src), "r"(sz) : "memory");
}
__device__ __forceinline__ void cp16(uint32_t dst, const void* src) {
    asm volatile("cp.async.cg.shared.global [%0], [%1], 16;"
                 :: "r"(dst), "l"(src) : "memory");
}
#define CP_COMMIT() asm volatile("cp.async.commit_group;" ::: "memory")
#define CP_WAIT0()  asm volatile("cp.async.wait_group 0;" ::: "memory")
#define CP_WAIT1()  asm volatile("cp.async.wait_group 1;" ::: "memory")

__device__ __forceinline__ void mma_f16(float* c, const uint32_t* a, const uint32_t* b) {
    asm volatile("mma.sync.aligned.m16n8k16.row.col.f32.f16.f16.f32 "
                 "{%0,%1,%2,%3}, {%4,%5,%6,%7}, {%8,%9}, {%0,%1,%2,%3};"
                 : "+f"(c[0]), "+f"(c[1]), "+f"(c[2]), "+f"(c[3])
                 : "r"(a[0]), "r"(a[1]), "r"(a[2]), "r"(a[3]), "r"(b[0]), "r"(b[1]));
}

__device__ __forceinline__ float gelu_erf(float v) {
    return 0.5f * v * (1.0f + erff(v * 0.70710678118654752f));
}

// ---------------------------------------------------------------------------
// Transpose tile body: in [R][C] fp32 -> out [C][R] fp16 for a 64(r) x 32(c)
// tile. float2-packed smem: both LDS phases conflict-free.
__device__ __forceinline__ void transpose_body(
    const float* __restrict__ in, __half* __restrict__ out,
    int R, int C, int z, int cb, int rb, float2 (*t2)[33], int tid) {
    size_t base = (size_t)z * R * C;
    in  += base; out += base;
    const int c0 = cb * 32, r0 = rb * 64;
    const int tx = tid & 31, ty = tid >> 5;    // 32 x 8
#pragma unroll
    for (int j = 0; j < 32; j += 8) {
        int rp = ty + j;
        float a = in[(size_t)(r0 + 2 * rp)     * C + c0 + tx];
        float b = in[(size_t)(r0 + 2 * rp + 1) * C + c0 + tx];
        t2[rp][tx] = make_float2(a, b);
    }
    __syncthreads();
#pragma unroll
    for (int j = 0; j < 32; j += 8) {
        int c = ty + j;
        float2 v = t2[tx][c];
        *(__half2*)(out + (size_t)(c0 + c) * R + r0 + 2 * tx) =
            __floats2half2_rn(v.x, v.y);
    }
}

// ---------------------------------------------------------------------------
// Prep kernel: router+cvt (1024 blocks) | W1 transpose (6144 blocks).
// W2 transpose is folded into GEMM1's early-exit blocks.
#define PREP_RTR    (T_ / 8)                  // 1024
#define PREP_TPB    768
#define PREP_TOTAL  (PREP_RTR + PREP_TPB * X_)

__global__ __launch_bounds__(256)
void prep_kernel(const float* __restrict__ x,
                 const float* __restrict__ Wr,
                 const float* __restrict__ br,
                 float* __restrict__ out_idx,
                 const float* __restrict__ W1) {
    __shared__ union {
        float2 t2[32][33];            // transpose tile (8448 B)
        float  sW[X_][E_];            // router: Wr transposed (32 KB)
    } sm;
    const int bx  = blockIdx.x;
    const int tid = threadIdx.x;

    if (bx >= PREP_RTR) {
        int idx = bx - PREP_RTR;               // W1 [E][H] -> [H][E]
        const int cbn = H_ / 32;               // 48
        const int z   = idx / PREP_TPB;
        const int rem = idx - z * PREP_TPB;
        const int rb  = rem / cbn;
        const int cb  = rem - rb * cbn;
        transpose_body(W1, g_W1T, E_, H_, z, cb, rb, sm.t2, tid);
        return;
    }

    // router role: stage Wr transposed into smem (once per block)
    for (int e = tid; e < E_; e += 256) {
        const float4* w4 = (const float4*)(Wr + (size_t)e * X_);
        float4 w0 = w4[0], w1 = w4[1];
        sm.sW[0][e] = w0.x; sm.sW[1][e] = w0.y;
        sm.sW[2][e] = w0.z; sm.sW[3][e] = w0.w;
        sm.sW[4][e] = w1.x; sm.sW[5][e] = w1.y;
        sm.sW[6][e] = w1.z; sm.sW[7][e] = w1.w;
    }
    __syncthreads();

    const int gwarp = bx * 8 + (tid >> 5);
    const int lane  = tid & 31;
    const float* xr = x + (size_t)gwarp * E_;
    __half* xh = g_xh + (size_t)gwarp * E_;

    float acc[X_];
#pragma unroll
    for (int j = 0; j < X_; j++) acc[j] = 0.f;
    for (int e = lane; e < E_; e += 32) {
        float v = xr[e];
        xh[e] = __float2half_rn(v);
#pragma unroll
        for (int j = 0; j < X_; j++) acc[j] += v * sm.sW[j][e];
    }
#pragma unroll
    for (int j = 0; j < X_; j++)
#pragma unroll
        for (int off = 16; off > 0; off >>= 1)
            acc[j] += __shfl_down_sync(0xffffffffu, acc[j], off);

    if (lane == 0) {
        float v0 = -3.0e38f, v1 = -3.0e38f;
        int   i0 = 0,        i1 = 0;
#pragma unroll
        for (int j = 0; j < X_; j++) {
            float v = acc[j] + br[j];
            if (v > v0)      { v1 = v0; i1 = i0; v0 = v; i0 = j; }
            else if (v > v1) { v1 = v;  i1 = j; }
        }
        if (out_idx) {
            out_idx[gwarp * K_ + 0] = (float)i0;
            out_idx[gwarp * K_ + 1] = (float)i1;
        }
        int p0 = atomicAdd(&g_count[i0], 1);
        g_slots[i0 * T_ + p0] = gwarp * K_ + 0;
        int p1 = atomicAdd(&g_count[i1], 1);
        g_slots[i1 * T_ + p1] = gwarp * K_ + 1;
    }
}

// ---------------------------------------------------------------------------
// fp16 mma.sync grouped GEMM: 128x128 tile, 256 threads (8 warps, 2x4 grid of
// 64x32 warp tiles), BK=64, 3-stage cp.async ring, scalar-LDS fragments.
// FIRST: C = gelu(xh @ W1T^T + b1) -> g_hh. Early-exit blocks become W2T
//        transpose workers (ticketed; W2T needed only by the next kernel).
// else : C = g_hh @ W2T^T + b2 -> g_yh (fp16); early-exit blocks return.
#define BKH      64
#define OP_WORDS (128 * 36)
#define STAGE_B  (2 * OP_WORDS * 4)
#define NSTAGE   3
#define GEMM_SMEM (1024 + NSTAGE * STAGE_B)
#define W2T_TICKETS (X_ * (H_ / 128) * (E_ / 32))   // 3072

template<int KDIM, int NDIM, bool FIRST>
__global__ __launch_bounds__(256)
void expert_gemm_h(const __half* __restrict__ WT_all,
                   const float* __restrict__ bias_all,
                   const float* __restrict__ W2src) {
    extern __shared__ char smx[];
    int*    sSlot = (int*)smx;
    float*  sBias = (float*)(smx + 512);
    char*   sData = smx + 1024;

    const int z    = blockIdx.z;
    const int cnt  = g_count[z];
    const int row0 = blockIdx.y * 128;
    const int tid  = threadIdx.x;

    if (row0 >= cnt) {
        if (!FIRST) return;
        // W2 transpose worker: consume 128x32 tiles by ticket.
        __shared__ int ts;
        float2 (*t2)[33] = (float2(*)[33])sData;
        for (;;) {
            __syncthreads();
            if (tid == 0) ts = atomicAdd(&g_ticket, 1);
            __syncthreads();
            const int t = ts;
            if (t >= W2T_TICKETS) return;
            const int wz  = t / 384;           // 384 = 12 * 32
            const int rem = t - wz * 384;
            const int rb  = rem >> 5;          // 128-row block (0..11)
            const int cb  = rem & 31;          // 32-col block
            transpose_body(W2src, g_W2T, H_, E_, wz, cb, rb * 2,     t2, tid);
            __syncthreads();
            transpose_body(W2src, g_W2T, H_, E_, wz, cb, rb * 2 + 1, t2, tid);
        }
    }

    const int jn0  = blockIdx.x * 128;
    const int lane = tid & 31;
    const int wid  = tid >> 5;

    if (tid < 128) {
        int r = row0 + tid;
        sSlot[tid] = (r < cnt) ? g_slots[z * T_ + r] : -1;
        sBias[tid] = bias_all[(size_t)z * NDIM + jn0 + tid];
    }
    __syncthreads();

    const __half* Abase = FIRST ? g_xh : g_hh;
    const __half* WT    = WT_all + (size_t)z * NDIM * KDIM;

    const uint32_t smb = smem_u32(sData);

    const __half* aSrc[4]; const __half* bSrc[4];
    uint32_t aSz[4], aDst[4], bDst[4];
#pragma unroll
    for (int j = 0; j < 4; j++) {
        int c = tid * 4 + j;
        int row = c >> 3, col = c & 7;
        int slot = sSlot[row];
        int arow = 0; uint32_t sz = 0;
        if (slot >= 0) { arow = FIRST ? (slot >> 1) : slot; sz = 16; }
        aSrc[j] = Abase + (size_t)arow * KDIM + col * 8;
        aSz[j]  = sz;
        bSrc[j] = WT + (size_t)(jn0 + row) * KDIM + col * 8;
        uint32_t o = (uint32_t)(row * 144 + col * 16);
        aDst[j] = smb + o;
        bDst[j] = smb + OP_WORDS * 4 + o;
    }

    constexpr int NC = KDIM / BKH;

#pragma unroll
    for (int st = 0; st < 2; st++) {
        uint32_t so = (uint32_t)(st * STAGE_B);
        const int k0 = st * BKH;
#pragma unroll
        for (int j = 0; j < 4; j++) {
            cp16z(aDst[j] + so, aSrc[j] + k0, aSz[j]);
            cp16 (bDst[j] + so, bSrc[j] + k0);
        }
        CP_COMMIT();
    }

    float acc[4][4][4];
#pragma unroll
    for (int mt = 0; mt < 4; mt++)
#pragma unroll
        for (int nt = 0; nt < 4; nt++)
#pragma unroll
            for (int q = 0; q < 4; q++) acc[mt][nt][q] = 0.f;

    const int warp_m = wid & 1;
    const int warp_n = wid >> 1;
    const int lr = lane >> 2;
    const int lc = lane & 3;

    int awBase[4], bwBase[4];
#pragma unroll
    for (int mt = 0; mt < 4; mt++)
        awBase[mt] = (warp_m * 64 + mt * 16 + lr) * 36 + lc;
#pragma unroll
    for (int nt = 0; nt < 4; nt++)
        bwBase[nt] = (warp_n * 32 + nt * 8 + lr) * 36 + lc;

    int stage = 0;
    for (int kc = 0; kc < NC; kc++) {
        if (kc + 1 < NC) { CP_WAIT1(); } else { CP_WAIT0(); }
        __syncthreads();

        if (kc + 2 < NC) {
            int st2 = stage + 2; if (st2 >= NSTAGE) st2 -= NSTAGE;
            uint32_t so = (uint32_t)(st2 * STAGE_B);
            const int k0 = (kc + 2) * BKH;
#pragma unroll
            for (int j = 0; j < 4; j++) {
                cp16z(aDst[j] + so, aSrc[j] + k0, aSz[j]);
                cp16 (bDst[j] + so, bSrc[j] + k0);
            }
            CP_COMMIT();
        }

        const uint32_t* As32 = (const uint32_t*)(sData + stage * STAGE_B);
        const uint32_t* Bs32 = As32 + OP_WORDS;

#pragma unroll
        for (int s = 0; s < 4; s++) {
            const int sk = s * 8;
            uint32_t afr[4][4];
#pragma unroll
            for (int mt = 0; mt < 4; mt++) {
                int w = awBase[mt] + sk;
                afr[mt][0] = As32[w];
                afr[mt][1] = As32[w + 8 * 36];
                afr[mt][2] = As32[w + 4];
                afr[mt][3] = As32[w + 8 * 36 + 4];
            }
            uint32_t bfr[4][2];
#pragma unroll
            for (int nt = 0; nt < 4; nt++) {
                int w = bwBase[nt] + sk;
                bfr[nt][0] = Bs32[w];
                bfr[nt][1] = Bs32[w + 4];
            }
#pragma unroll
            for (int mt = 0; mt < 4; mt++)
#pragma unroll
                for (int nt = 0; nt < 4; nt++)
                    mma_f16(acc[mt][nt], afr[mt], bfr[nt]);
        }

        stage++; if (stage >= NSTAGE) stage -= NSTAGE;
    }

    // epilogue: bias + (gelu) -> fp16 scatter
#pragma unroll
    for (int mt = 0; mt < 4; mt++) {
        const int rb = warp_m * 64 + mt * 16 + lr;
#pragma unroll
        for (int half_i = 0; half_i < 2; half_i++) {
            int r    = rb + half_i * 8;
            int slot = sSlot[r];
            if (slot < 0) continue;
#pragma unroll
            for (int nt = 0; nt < 4; nt++) {
                int cidx = warp_n * 32 + nt * 8 + 2 * lc;
                float v0 = acc[mt][nt][half_i * 2 + 0] + sBias[cidx];
                float v1 = acc[mt][nt][half_i * 2 + 1] + sBias[cidx + 1];
                if (FIRST) {
                    __half2 hv = __floats2half2_rn(gelu_erf(v0), gelu_erf(v1));
                    *(__half2*)(g_hh + (size_t)slot * NDIM + jn0 + cidx) = hv;
                } else {
                    __half2 hv = __floats2half2_rn(v0, v1);
                    *(__half2*)(g_yh + (size_t)slot * NDIM + jn0 + cidx) = hv;
                }
            }
        }
    }
}

// ---------------------------------------------------------------------------
// One block per token: out[t,e] = 0.5*(y[2t,e]+y[2t+1,e]). Block 0 re-zeroes
// scheduler state (first launch relies on load-time zero-init).
__global__ __launch_bounds__(128)
void reduce_kernel(float* __restrict__ out) {
    const int t   = blockIdx.x;
    const int tid = threadIdx.x;
    if (t == 0) {
        if (tid < X_) g_count[tid] = 0;
        if (tid == X_) g_ticket = 0;
    }
    const __half2* ya = (const __half2*)(g_yh + (size_t)(2 * t)     * E_) + tid * 4;
    const __half2* yb = (const __half2*)(g_yh + (size_t)(2 * t + 1) * E_) + tid * 4;
    float4 r0, r1;
#pragma unroll
    for (int q = 0; q < 4; q++) {
        float2 a = __half22float2(ya[q]);
        float2 b = __half22float2(yb[q]);
        float rx = 0.5f * (a.x + b.x);
        float ry = 0.5f * (a.y + b.y);
        if (q == 0) { r0.x = rx; r0.y = ry; }
        else if (q == 1) { r0.z = rx; r0.w = ry; }
        else if (q == 2) { r1.x = rx; r1.y = ry; }
        else { r1.z = rx; r1.w = ry; }
    }
    float4* o = (float4*)(out + (size_t)t * E_ + tid * 8);
    o[0] = r0; o[1] = r1;
}

// ---------------------------------------------------------------------------
extern "C" void kernel_launch(void* const* d_in, const int* in_sizes, int n_in,
                              void* d_out, int out_size) {
    const float* x  = (const float*)d_in[0];
    const float* Wr = (const float*)d_in[1];
    const float* br = (const float*)d_in[2];
    const float* W1 = (const float*)d_in[3];
    const float* b1 = (const float*)d_in[4];
    const float* W2 = (const float*)d_in[5];
    const float* b2 = (const float*)d_in[6];
    float* out = (float*)d_out;

    float* idx_out = (out_size >= (int)((size_t)T_ * E_ + T_ * K_))
                         ? out + (size_t)T_ * E_ : nullptr;

    static __half* w1t_arg = nullptr;
    static __half* w2t_arg = nullptr;
    if (!w1t_arg) {
        cudaGetSymbolAddress((void**)&w1t_arg, g_W1T);
        cudaGetSymbolAddress((void**)&w2t_arg, g_W2T);
        cudaFuncSetAttribute(expert_gemm_h<E_, H_, true>,
                             cudaFuncAttributeMaxDynamicSharedMemorySize, GEMM_SMEM);
        cudaFuncSetAttribute(expert_gemm_h<H_, E_, false>,
                             cudaFuncAttributeMaxDynamicSharedMemorySize, GEMM_SMEM);
    }

    prep_kernel<<<PREP_TOTAL, 256>>>(x, Wr, br, idx_out, W1);

    expert_gemm_h<E_, H_, true ><<<dim3(H_ / 128, T_ / 128, X_), 256, GEMM_SMEM>>>(
        w1t_arg, b1, W2);
    expert_gemm_h<H_, E_, false><<<dim3(E_ / 128, T_ / 128, X_), 256, GEMM_SMEM>>>(
        w2t_arg, b2, nullptr);

    reduce_kernel<<<T_, 128>>>(out);
}